// round 5
// baseline (speedup 1.0000x reference)
#include <cuda_runtime.h>
#include <cstdint>

// ============================================================================
// StableFourierConvSSM fused kernel, round 5.
// Same mma.sync m16n8k8 tf32 core as round 4 (351us), mainloop restructured:
//   - kt-outer / gate-inner: A-fragments + tf32 CVTs loaded ONCE per kt and
//     shared across the 3 gate GEMMs (was 3x redundant).
//   - sX pair-interleaved float2 (k, k+4) -> A-frags are 4x LDS.64 per kt.
//   - B-fragments loaded directly from pre-paired __device__ g_Wpk via
//     LDG.64 (L1/L2-resident, 100% sector efficiency); no smem W panel,
//     no W staging, no mainloop __syncthreads at all.
//   - smem = 71KB (sX + bias); __launch_bounds__(256,2) pins 2 CTAs/SM.
// Epilogue and GEMM math unchanged -> rel_err expected bit-identical.
// Shapes: B=16, H=128, W=128, C=64, C2=128, K=7, T=16.
// ============================================================================

#define SXP_STRIDE 68   // float2 stride; 68 % 16 == 4 -> conflict-free LDS.64
#define SMEM_BYTES (128 * SXP_STRIDE * 8 + 384 * 4)   // 71,168 B

// Packed freq kernels, layout [h][c][w] float4 = (Ar, Ai, Br, Bi)
__device__ float4 g_AB[128 * 64 * 128];
// Separable-DFT intermediate, layout [(u*7+q)*64 + c]
__device__ float g_GAr[128 * 7 * 64];
__device__ float g_GAi[128 * 7 * 64];
__device__ float g_GBr[128 * 7 * 64];
__device__ float g_GBi[128 * 7 * 64];
// Pre-paired tf32 W panels: [(gate*2+hf)][kp=64][jc=64] float2 = (k, k+4)
__device__ float2 g_Wpk[6 * 64 * 64];

__device__ __forceinline__ uint32_t f2tf32(float x) {
    uint32_t u;
    asm("cvt.rna.tf32.f32 %0, %1;" : "=r"(u) : "f"(x));
    return u;
}

__device__ __forceinline__ void mma_tf32(float d[4], const uint32_t a[4],
                                         uint32_t b0, uint32_t b1) {
    asm("mma.sync.aligned.m16n8k8.row.col.f32.tf32.tf32.f32 "
        "{%0,%1,%2,%3}, {%4,%5,%6,%7}, {%8,%9}, {%0,%1,%2,%3};"
        : "+f"(d[0]), "+f"(d[1]), "+f"(d[2]), "+f"(d[3])
        : "r"(a[0]), "r"(a[1]), "r"(a[2]), "r"(a[3]), "r"(b0), "r"(b1));
}

__device__ __forceinline__ float sigm_f(float z) {
    return __fdividef(1.0f, 1.0f + __expf(-z));
}
__device__ __forceinline__ float softplus_f(float z) {
    return (z > 20.0f) ? z : __logf(1.0f + __expf(z));
}

// ---------------------------------------------------------------------------
// W pre-pack: permuted cols (adjacent = real/imag of one channel), tf32-
// rounded, (k, k+4) pair-interleaved for LDG.64 B-frags.
// idx -> panel(gate,hf), kp(kt,t4), jc. value.x = W[kt*8+t4][c], .y = W[+4][c]
// ---------------------------------------------------------------------------
__global__ void pack_w(const float* __restrict__ Wf, const float* __restrict__ Wi,
                       const float* __restrict__ Wd) {
    int idx = blockIdx.x * 256 + threadIdx.x;     // 0..24575
    int panel = idx >> 12;
    int rem = idx & 4095;
    int kp = rem >> 6, jc = rem & 63;
    int gate = panel >> 1, hf = panel & 1;
    const float* W = (gate == 0) ? Wf : (gate == 1) ? Wi : Wd;
    int k = (kp >> 2) * 8 + (kp & 3);
    int c = hf * 32 + (jc >> 1) + ((jc & 1) << 6);
    g_Wpk[idx] = make_float2(__uint_as_float(f2tf32(W[k * 128 + c])),
                             __uint_as_float(f2tf32(W[(k + 4) * 128 + c])));
}

// ---------------------------------------------------------------------------
// Stage 1: G[c,u,q] = sum_p kern[c,p,q] * exp(-2*pi*i * u*(p+60)/128)
// ---------------------------------------------------------------------------
__global__ void freq_rows(const float* __restrict__ A_real, const float* __restrict__ A_imag,
                          const float* __restrict__ B_real, const float* __restrict__ B_imag) {
    __shared__ float tc[128], ts[128];
    int t = threadIdx.x;  // 64
    for (int k = t; k < 128; k += 64) {
        float s, c;
        sincospif((float)k / 64.0f, &s, &c);  // angle = 2*pi*k/128
        tc[k] = c; ts[k] = s;
    }
    __syncthreads();
    int u = blockIdx.x / 7, q = blockIdx.x % 7, c = t;
    float gar = 0.f, gai = 0.f, gbr = 0.f, gbi = 0.f;
#pragma unroll
    for (int p = 0; p < 7; ++p) {
        int idx = (u * (p + 60)) & 127;
        float co = tc[idx], si = ts[idx];  // exp(-i t) = co - i si
        float kr = A_real[c * 49 + p * 7 + q], ki = A_imag[c * 49 + p * 7 + q];
        gar += kr * co + ki * si; gai += ki * co - kr * si;
        kr = B_real[c * 49 + p * 7 + q]; ki = B_imag[c * 49 + p * 7 + q];
        gbr += kr * co + ki * si; gbi += ki * co - kr * si;
    }
    int o = (u * 7 + q) * 64 + c;
    g_GAr[o] = gar; g_GAi[o] = gai; g_GBr[o] = gbr; g_GBi[o] = gbi;
}

// ---------------------------------------------------------------------------
// Stage 2: col DFT + A stability scaling; store packed [h][c][w] float4.
// ---------------------------------------------------------------------------
__global__ void freq_cols() {
    __shared__ float tc[128], ts[128];
    int t = threadIdx.x;  // 64
    for (int k = t; k < 128; k += 64) {
        float s, c;
        sincospif((float)k / 64.0f, &s, &c);
        tc[k] = c; ts[k] = s;
    }
    __syncthreads();
    int u = blockIdx.x >> 7, v = blockIdx.x & 127, c = t;
    float ar = 0.f, ai = 0.f, br = 0.f, bi = 0.f;
#pragma unroll
    for (int q = 0; q < 7; ++q) {
        int idx = (v * (q + 60)) & 127;
        float co = tc[idx], si = ts[idx];
        int o = (u * 7 + q) * 64 + c;
        float gr = g_GAr[o], gi = g_GAi[o];
        ar += gr * co + gi * si; ai += gi * co - gr * si;
        gr = g_GBr[o]; gi = g_GBi[o];
        br += gr * co + gi * si; bi += gi * co - gr * si;
    }
    float mag = sqrtf(ar * ar + ai * ai + 1e-8f);
    float sc = 0.95f * (1.0f / (1.0f + expf(-mag))) / (mag + 1e-8f);
    g_AB[(u * 64 + c) * 128 + v] = make_float4(ar * sc, ai * sc, br, bi);
}

// ---------------------------------------------------------------------------
// Fused main. One CTA per (b,h): M=128 w-rows, K=128, 3 gate GEMMs N=64/hf.
// 8 warps: wm=warp>>1 (32-row strip), wn=warp&1 (32-col half of 64-col panel).
// ---------------------------------------------------------------------------
__global__ void __launch_bounds__(256, 2)
fused_main(const float* __restrict__ x,
           const float* __restrict__ bf, const float* __restrict__ bi_,
           const float* __restrict__ bd, float* __restrict__ out) {
    extern __shared__ __align__(16) float smem[];
    float2* sXp = (float2*)smem;                       // [128][SXP_STRIDE] f2
    float*  sXf = smem;                                // scalar view
    float*  sB  = smem + 128 * SXP_STRIDE * 2;         // [384] biases

    const int tid = threadIdx.x;
    const int b = blockIdx.x >> 7;
    const int h = blockIdx.x & 127;

    // ---- stage x tile pair-interleaved: pair p=4j+t holds (k=8j+t, 8j+t+4)
    {
        const float4* x4 = (const float4*)(x + ((size_t)(b * 128 + h)) * 16384);
        for (int i = tid; i < 2048; i += 256) {
            int w = i >> 4, j = i & 15;
            float4 lo = x4[w * 32 + 2 * j];
            float4 hi = x4[w * 32 + 2 * j + 1];
            float2* d = sXp + w * SXP_STRIDE + 4 * j;
            d[0] = make_float2(lo.x, hi.x);
            d[1] = make_float2(lo.y, hi.y);
            d[2] = make_float2(lo.z, hi.z);
            d[3] = make_float2(lo.w, hi.w);
        }
        for (int i = tid; i < 384; i += 256)
            sB[i] = (i < 128) ? bf[i] : (i < 256) ? bi_[i - 128] : bd[i - 256];
    }
    __syncthreads();

    const int lane = tid & 31;
    const int warp = tid >> 5;
    const int g = lane >> 2;       // row within 8
    const int t4 = lane & 3;
    const int wm = warp >> 1;      // 32-row strip
    const int wn = warp & 1;       // 32-col half
    const int rbase = wm * 32;

    for (int hf = 0; hf < 2; ++hf) {
        float acc[3][2][4][4];  // [gate][mtile][ntile][frag]
#pragma unroll
        for (int gate = 0; gate < 3; ++gate)
#pragma unroll
            for (int mt = 0; mt < 2; ++mt)
#pragma unroll
                for (int nt = 0; nt < 4; ++nt)
#pragma unroll
                    for (int r = 0; r < 4; ++r)
                        acc[gate][mt][nt][r] = 0.0f;

        const float2* W0 = g_Wpk + (0 * 2 + hf) * 4096;
        const float2* W1 = g_Wpk + (1 * 2 + hf) * 4096;
        const float2* W2 = g_Wpk + (2 * 2 + hf) * 4096;

#pragma unroll 4
        for (int kt = 0; kt < 16; ++kt) {
            const int kp = kt * 4 + t4;
            // A-fragments: shared by all 3 gates (4 x LDS.64 + 8 CVT)
            uint32_t a[2][4];
#pragma unroll
            for (int mt = 0; mt < 2; ++mt) {
                float2 lo = sXp[(rbase + 16 * mt + g) * SXP_STRIDE + kp];
                float2 hi = sXp[(rbase + 16 * mt + g + 8) * SXP_STRIDE + kp];
                a[mt][0] = f2tf32(lo.x);
                a[mt][1] = f2tf32(hi.x);
                a[mt][2] = f2tf32(lo.y);
                a[mt][3] = f2tf32(hi.y);
            }
            const int bidx = kp * 64 + wn * 32 + g;
#pragma unroll
            for (int nt = 0; nt < 4; ++nt) {
                float2 b0 = W0[bidx + nt * 8];
                float2 b1 = W1[bidx + nt * 8];
                float2 b2 = W2[bidx + nt * 8];
                mma_tf32(acc[0][0][nt], a[0], __float_as_uint(b0.x), __float_as_uint(b0.y));
                mma_tf32(acc[0][1][nt], a[1], __float_as_uint(b0.x), __float_as_uint(b0.y));
                mma_tf32(acc[1][0][nt], a[0], __float_as_uint(b1.x), __float_as_uint(b1.y));
                mma_tf32(acc[1][1][nt], a[1], __float_as_uint(b1.x), __float_as_uint(b1.y));
                mma_tf32(acc[2][0][nt], a[0], __float_as_uint(b2.x), __float_as_uint(b2.y));
                mma_tf32(acc[2][1][nt], a[1], __float_as_uint(b2.x), __float_as_uint(b2.y));
            }
        }

        // ---- epilogue: activations + complex input + T=16 recurrence ----
#pragma unroll
        for (int mt = 0; mt < 2; ++mt)
#pragma unroll
            for (int rr = 0; rr < 2; ++rr)
#pragma unroll
                for (int nt = 0; nt < 4; ++nt) {
                    const int w = rbase + 16 * mt + g + 8 * rr;
                    const int m = hf * 32 + wn * 16 + nt * 4 + t4;  // channel

                    float zf_r = acc[0][mt][nt][2 * rr];
                    float zf_i = acc[0][mt][nt][2 * rr + 1];
                    float zi_r = acc[1][mt][nt][2 * rr];
                    float zi_i = acc[1][mt][nt][2 * rr + 1];
                    float zd_r = acc[2][mt][nt][2 * rr];
                    float zd_i = acc[2][mt][nt][2 * rr + 1];

                    float fg_r = sigm_f(zf_r + sB[m] + 2.0f);
                    float fg_i = sigm_f(zf_i + sB[m + 64] + 2.0f);
                    float ig_r = sigm_f(zi_r + sB[128 + m]);
                    float ig_i = sigm_f(zi_i + sB[128 + m + 64]);
                    float dl_r = 0.1f * softplus_f(zd_r + sB[256 + m]);
                    float dl_i = 0.1f * softplus_f(zd_i + sB[256 + m + 64]);

                    // exact x from pair-interleaved panel
                    const int pidx = ((m >> 3) << 2) + (m & 3);
                    const int comp = (m >> 2) & 1;
                    float x_r = sXf[(w * SXP_STRIDE + pidx) * 2 + comp];
                    float x_i = sXf[(w * SXP_STRIDE + pidx + 32) * 2 + comp];

                    float4 AB = g_AB[(h * 64 + m) * 128 + w];  // (Ar,Ai,Br,Bi)

                    float Bx_r = AB.z * x_r - AB.w * x_i;
                    float Bx_i = AB.z * x_i + AB.w * x_r;
                    float inp_r = dl_r * ig_r * Bx_r;
                    float inp_i = dl_i * ig_i * Bx_i;

                    float m11 = fg_r * AB.x, m12 = -fg_r * AB.y;
                    float m21 = fg_i * AB.y, m22 = fg_i * AB.x;

                    float hr = inp_r, hi = inp_i;  // step 1 from h0 = 0
#pragma unroll
                    for (int t = 1; t < 16; ++t) {
                        float nr = fmaf(m11, hr, fmaf(m12, hi, inp_r));
                        float ni = fmaf(m21, hr, fmaf(m22, hi, inp_i));
                        hr = nr; hi = ni;
                    }

                    size_t ob = ((size_t)(b * 128 + h) * 128 + w) * 128;
                    out[ob + m] = hr;
                    out[ob + m + 64] = hi;
                }
    }
}

// ---------------------------------------------------------------------------
// Launch. Inputs: x_ri, Wf, bf, Wi, bi, Wd, bd, A_real, A_imag, B_real, B_imag
// ---------------------------------------------------------------------------
extern "C" void kernel_launch(void* const* d_in, const int* in_sizes, int n_in,
                              void* d_out, int out_size) {
    (void)in_sizes; (void)n_in; (void)out_size;
    const float* x      = (const float*)d_in[0];
    const float* Wf     = (const float*)d_in[1];
    const float* bf     = (const float*)d_in[2];
    const float* Wi     = (const float*)d_in[3];
    const float* bi     = (const float*)d_in[4];
    const float* Wd     = (const float*)d_in[5];
    const float* bd     = (const float*)d_in[6];
    const float* A_real = (const float*)d_in[7];
    const float* A_imag = (const float*)d_in[8];
    const float* B_real = (const float*)d_in[9];
    const float* B_imag = (const float*)d_in[10];
    float* out = (float*)d_out;

    cudaFuncSetAttribute(fused_main, cudaFuncAttributeMaxDynamicSharedMemorySize,
                         SMEM_BYTES);

    pack_w<<<96, 256>>>(Wf, Wi, Wd);
    freq_rows<<<128 * 7, 64>>>(A_real, A_imag, B_real, B_imag);
    freq_cols<<<128 * 128, 64>>>();
    fused_main<<<16 * 128, 256, SMEM_BYTES>>>(x, bf, bi, bd, out);
}

// round 7
// speedup vs baseline: 1.6101x; 1.6101x over previous
#include <cuda_runtime.h>
#include <cstdint>

// ============================================================================
// StableFourierConvSSM fused kernel, round 7 — byte-identical resubmit of
// round 6 (infra "container failed twice", same pure-infra signature as
// round 1; no ptxas/harness output implicating the kernel).
// Base = round 4 (351us, smem-staged W panels — round 5 proved per-thread LDG
// B-frags are a regression). Changes vs round 4:
//   - sX and sW both pair-interleaved (k, k+4) float2, stride 68 (=4 mod 16,
//     conflict-free LDS.64 in both phases): A-frags 4xLDS.64, B-frags
//     4xLDS.64 per gate per kt (was 16x LDS.32 + 8 CVT).
//   - x pre-converted to tf32 at staging (CVT once, not per gate).
//   - epilogue reads exact fp32 x from global (L1/L2-hot tile).
//   - recurrence packed 2 sites per fma.rn.f32x2 (PTX 8.6, sm_100 family):
//     half the FFMA count, per-lane IEEE-identical.
// Shapes: B=16, H=128, W=128, C=64, C2=128, K=7, T=16.
// ============================================================================

#define SXP_STRIDE 68   // float2 stride; 68 % 16 == 4 -> conflict-free LDS.64
#define SWP_STRIDE 68
#define SMEM_BYTES (128 * SXP_STRIDE * 8 + 64 * SWP_STRIDE * 8 + 384 * 4)  // 105,984

// Packed freq kernels, layout [h][c][w] float4 = (Ar, Ai, Br, Bi)
__device__ float4 g_AB[128 * 64 * 128];
// Separable-DFT intermediate, layout [(u*7+q)*64 + c]
__device__ float g_GAr[128 * 7 * 64];
__device__ float g_GAi[128 * 7 * 64];
__device__ float g_GBr[128 * 7 * 64];
__device__ float g_GBi[128 * 7 * 64];
// Pre-paired tf32 W panels: [(gate*2+hf)][kp=64][jc=64] float2 = (k, k+4)
__device__ float2 g_Wpk[6 * 64 * 64];

__device__ __forceinline__ uint32_t f2tf32(float x) {
    uint32_t u;
    asm("cvt.rna.tf32.f32 %0, %1;" : "=r"(u) : "f"(x));
    return u;
}

__device__ __forceinline__ void mma_tf32(float d[4], const uint32_t a[4],
                                         uint32_t b0, uint32_t b1) {
    asm("mma.sync.aligned.m16n8k8.row.col.f32.tf32.tf32.f32 "
        "{%0,%1,%2,%3}, {%4,%5,%6,%7}, {%8,%9}, {%0,%1,%2,%3};"
        : "+f"(d[0]), "+f"(d[1]), "+f"(d[2]), "+f"(d[3])
        : "r"(a[0]), "r"(a[1]), "r"(a[2]), "r"(a[3]), "r"(b0), "r"(b1));
}

// ---- packed f32x2 (PTX ISA 8.6, sm_100 family) ----
__device__ __forceinline__ unsigned long long pk2(float lo, float hi) {
    unsigned long long r;
    asm("mov.b64 %0, {%1, %2};" : "=l"(r) : "f"(lo), "f"(hi));
    return r;
}
__device__ __forceinline__ void unpk2(unsigned long long v, float& lo, float& hi) {
    asm("mov.b64 {%0, %1}, %2;" : "=f"(lo), "=f"(hi) : "l"(v));
}
__device__ __forceinline__ unsigned long long ffma2(unsigned long long a,
                                                    unsigned long long b,
                                                    unsigned long long c) {
    unsigned long long d;
    asm("fma.rn.f32x2 %0, %1, %2, %3;" : "=l"(d) : "l"(a), "l"(b), "l"(c));
    return d;
}

__device__ __forceinline__ float sigm_f(float z) {
    return __fdividef(1.0f, 1.0f + __expf(-z));
}
__device__ __forceinline__ float softplus_f(float z) {
    return (z > 20.0f) ? z : __logf(1.0f + __expf(z));
}

// ---------------------------------------------------------------------------
// W pre-pack: permuted cols (adjacent = real/imag of one channel), tf32-
// rounded, (k, k+4) pair-interleaved.
// ---------------------------------------------------------------------------
__global__ void pack_w(const float* __restrict__ Wf, const float* __restrict__ Wi,
                       const float* __restrict__ Wd) {
    int idx = blockIdx.x * 256 + threadIdx.x;     // 0..24575
    int panel = idx >> 12;
    int rem = idx & 4095;
    int kp = rem >> 6, jc = rem & 63;
    int gate = panel >> 1, hf = panel & 1;
    const float* W = (gate == 0) ? Wf : (gate == 1) ? Wi : Wd;
    int k = (kp >> 2) * 8 + (kp & 3);
    int c = hf * 32 + (jc >> 1) + ((jc & 1) << 6);
    g_Wpk[idx] = make_float2(__uint_as_float(f2tf32(W[k * 128 + c])),
                             __uint_as_float(f2tf32(W[(k + 4) * 128 + c])));
}

// ---------------------------------------------------------------------------
// Stage 1: G[c,u,q] = sum_p kern[c,p,q] * exp(-2*pi*i * u*(p+60)/128)
// ---------------------------------------------------------------------------
__global__ void freq_rows(const float* __restrict__ A_real, const float* __restrict__ A_imag,
                          const float* __restrict__ B_real, const float* __restrict__ B_imag) {
    __shared__ float tc[128], ts[128];
    int t = threadIdx.x;  // 64
    for (int k = t; k < 128; k += 64) {
        float s, c;
        sincospif((float)k / 64.0f, &s, &c);
        tc[k] = c; ts[k] = s;
    }
    __syncthreads();
    int u = blockIdx.x / 7, q = blockIdx.x % 7, c = t;
    float gar = 0.f, gai = 0.f, gbr = 0.f, gbi = 0.f;
#pragma unroll
    for (int p = 0; p < 7; ++p) {
        int idx = (u * (p + 60)) & 127;
        float co = tc[idx], si = ts[idx];  // exp(-i t) = co - i si
        float kr = A_real[c * 49 + p * 7 + q], ki = A_imag[c * 49 + p * 7 + q];
        gar += kr * co + ki * si; gai += ki * co - kr * si;
        kr = B_real[c * 49 + p * 7 + q]; ki = B_imag[c * 49 + p * 7 + q];
        gbr += kr * co + ki * si; gbi += ki * co - kr * si;
    }
    int o = (u * 7 + q) * 64 + c;
    g_GAr[o] = gar; g_GAi[o] = gai; g_GBr[o] = gbr; g_GBi[o] = gbi;
}

// ---------------------------------------------------------------------------
// Stage 2: col DFT + A stability scaling; store packed [h][c][w] float4.
// ---------------------------------------------------------------------------
__global__ void freq_cols() {
    __shared__ float tc[128], ts[128];
    int t = threadIdx.x;  // 64
    for (int k = t; k < 128; k += 64) {
        float s, c;
        sincospif((float)k / 64.0f, &s, &c);
        tc[k] = c; ts[k] = s;
    }
    __syncthreads();
    int u = blockIdx.x >> 7, v = blockIdx.x & 127, c = t;
    float ar = 0.f, ai = 0.f, br = 0.f, bi = 0.f;
#pragma unroll
    for (int q = 0; q < 7; ++q) {
        int idx = (v * (q + 60)) & 127;
        float co = tc[idx], si = ts[idx];
        int o = (u * 7 + q) * 64 + c;
        float gr = g_GAr[o], gi = g_GAi[o];
        ar += gr * co + gi * si; ai += gi * co - gr * si;
        gr = g_GBr[o]; gi = g_GBi[o];
        br += gr * co + gi * si; bi += gi * co - gr * si;
    }
    float mag = sqrtf(ar * ar + ai * ai + 1e-8f);
    float sc = 0.95f * (1.0f / (1.0f + expf(-mag))) / (mag + 1e-8f);
    g_AB[(u * 64 + c) * 128 + v] = make_float4(ar * sc, ai * sc, br, bi);
}

// ---------------------------------------------------------------------------
// Fused main. One CTA per (b,h): M=128 w-rows, K=128, 3 gate GEMMs N=64/hf.
// 8 warps: wm=warp>>1 (32-row strip), wn=warp&1 (32-col half of 64-col panel).
// ---------------------------------------------------------------------------
__global__ void __launch_bounds__(256, 2)
fused_main(const float* __restrict__ x,
           const float* __restrict__ bf, const float* __restrict__ bi_,
           const float* __restrict__ bd, float* __restrict__ out) {
    extern __shared__ __align__(16) float smem[];
    float2* sXp = (float2*)smem;                               // [128][68] tf32 pairs
    float2* sWp = (float2*)(smem + 128 * SXP_STRIDE * 2);      // [64][68] W pairs
    float*  sB  = smem + 128 * SXP_STRIDE * 2 + 64 * SWP_STRIDE * 2;  // [384]

    const int tid = threadIdx.x;
    const int b = blockIdx.x >> 7;
    const int h = blockIdx.x & 127;
    const float* xg = x + ((size_t)(b * 128 + h)) * 16384;

    // ---- stage x: pair (k, k+4), PRE-CONVERTED to tf32 bits ----
    {
        const float4* x4 = (const float4*)xg;
        for (int i = tid; i < 2048; i += 256) {
            int w = i >> 4, j = i & 15;
            float4 lo = x4[w * 32 + 2 * j];
            float4 hi = x4[w * 32 + 2 * j + 1];
            float4 p0 = make_float4(__uint_as_float(f2tf32(lo.x)), __uint_as_float(f2tf32(hi.x)),
                                    __uint_as_float(f2tf32(lo.y)), __uint_as_float(f2tf32(hi.y)));
            float4 p1 = make_float4(__uint_as_float(f2tf32(lo.z)), __uint_as_float(f2tf32(hi.z)),
                                    __uint_as_float(f2tf32(lo.w)), __uint_as_float(f2tf32(hi.w)));
            float4* d = (float4*)(sXp + w * SXP_STRIDE + 4 * j);
            d[0] = p0; d[1] = p1;
        }
        for (int i = tid; i < 384; i += 256)
            sB[i] = (i < 128) ? bf[i] : (i < 256) ? bi_[i - 128] : bd[i - 256];
    }

    const int lane = tid & 31;
    const int warp = tid >> 5;
    const int g = lane >> 2;       // row within 8
    const int t4 = lane & 3;
    const int wm = warp >> 1;      // 32-row strip
    const int wn = warp & 1;       // 32-col half
    const int rbase = wm * 32;

    for (int hf = 0; hf < 2; ++hf) {
        float acc[3][2][4][4];  // [gate][mtile][ntile][frag]
#pragma unroll
        for (int gate = 0; gate < 3; ++gate)
#pragma unroll
            for (int mt = 0; mt < 2; ++mt)
#pragma unroll
                for (int nt = 0; nt < 4; ++nt)
#pragma unroll
                    for (int r = 0; r < 4; ++r)
                        acc[gate][mt][nt][r] = 0.0f;

        for (int gate = 0; gate < 3; ++gate) {
            __syncthreads();  // prev panel consumed (and x staged, first time)
            // stage pre-paired W panel: straight float4 copy with stride-68
            {
                const float4* src = (const float4*)(g_Wpk + (gate * 2 + hf) * 4096);
                for (int i = tid; i < 2048; i += 256) {
                    int kp = i >> 5, jc = (2 * i) & 63;
                    *(float4*)(sWp + kp * SWP_STRIDE + jc) = src[i];
                }
            }
            __syncthreads();

#pragma unroll 4
            for (int kt = 0; kt < 16; ++kt) {
                const int kp = kt * 4 + t4;
                uint32_t a[2][4];
#pragma unroll
                for (int mt = 0; mt < 2; ++mt) {
                    float2 lo = sXp[(rbase + 16 * mt + g) * SXP_STRIDE + kp];
                    float2 hi = sXp[(rbase + 16 * mt + g + 8) * SXP_STRIDE + kp];
                    a[mt][0] = __float_as_uint(lo.x);
                    a[mt][1] = __float_as_uint(hi.x);
                    a[mt][2] = __float_as_uint(lo.y);
                    a[mt][3] = __float_as_uint(hi.y);
                }
                const int bofs = kp * SWP_STRIDE + wn * 32 + g;
#pragma unroll
                for (int nt = 0; nt < 4; ++nt) {
                    float2 bb = sWp[bofs + nt * 8];
                    mma_tf32(acc[gate][0][nt], a[0],
                             __float_as_uint(bb.x), __float_as_uint(bb.y));
                    mma_tf32(acc[gate][1][nt], a[1],
                             __float_as_uint(bb.x), __float_as_uint(bb.y));
                }
            }
        }

        // ---- epilogue: activations + complex input + packed T=16 recurrence
#pragma unroll
        for (int mt = 0; mt < 2; ++mt)
#pragma unroll
            for (int nt = 0; nt < 4; ++nt) {
                const int m = hf * 32 + wn * 16 + nt * 4 + t4;  // channel 0..63
                const float bfr = sB[m] + 2.0f, bfi = sB[m + 64] + 2.0f;
                const float bir = sB[128 + m], bii = sB[128 + m + 64];
                const float bdr = sB[256 + m], bdi = sB[256 + m + 64];

                float M11[2], M12[2], M21[2], M22[2], IR[2], II[2];
                int wrow[2];
#pragma unroll
                for (int rr = 0; rr < 2; ++rr) {
                    const int w = rbase + 16 * mt + g + 8 * rr;
                    wrow[rr] = w;
                    float fg_r = sigm_f(acc[0][mt][nt][2 * rr] + bfr);
                    float fg_i = sigm_f(acc[0][mt][nt][2 * rr + 1] + bfi);
                    float ig_r = sigm_f(acc[1][mt][nt][2 * rr] + bir);
                    float ig_i = sigm_f(acc[1][mt][nt][2 * rr + 1] + bii);
                    float dl_r = 0.1f * softplus_f(acc[2][mt][nt][2 * rr] + bdr);
                    float dl_i = 0.1f * softplus_f(acc[2][mt][nt][2 * rr + 1] + bdi);

                    float x_r = xg[w * 128 + m];        // exact fp32 (L1/L2 hot)
                    float x_i = xg[w * 128 + m + 64];
                    float4 AB = g_AB[(h * 64 + m) * 128 + w];  // (Ar,Ai,Br,Bi)

                    float Bx_r = AB.z * x_r - AB.w * x_i;
                    float Bx_i = AB.z * x_i + AB.w * x_r;
                    IR[rr] = dl_r * ig_r * Bx_r;
                    II[rr] = dl_i * ig_i * Bx_i;
                    M11[rr] = fg_r * AB.x; M12[rr] = -fg_r * AB.y;
                    M21[rr] = fg_i * AB.y; M22[rr] = fg_i * AB.x;
                }

                // two independent sites per f32x2 lane-pair
                unsigned long long pm11 = pk2(M11[0], M11[1]);
                unsigned long long pm12 = pk2(M12[0], M12[1]);
                unsigned long long pm21 = pk2(M21[0], M21[1]);
                unsigned long long pm22 = pk2(M22[0], M22[1]);
                unsigned long long pir  = pk2(IR[0], IR[1]);
                unsigned long long pii  = pk2(II[0], II[1]);
                unsigned long long vr = pir, vi = pii;  // step 1 from h0 = 0
#pragma unroll
                for (int t = 1; t < 16; ++t) {
                    unsigned long long nr = ffma2(pm11, vr, ffma2(pm12, vi, pir));
                    unsigned long long ni = ffma2(pm21, vr, ffma2(pm22, vi, pii));
                    vr = nr; vi = ni;
                }
                float hr0, hr1, hi0, hi1;
                unpk2(vr, hr0, hr1);
                unpk2(vi, hi0, hi1);

                size_t ob0 = ((size_t)(b * 128 + h) * 128 + wrow[0]) * 128;
                size_t ob1 = ((size_t)(b * 128 + h) * 128 + wrow[1]) * 128;
                out[ob0 + m] = hr0; out[ob0 + m + 64] = hi0;
                out[ob1 + m] = hr1; out[ob1 + m + 64] = hi1;
            }
    }
}

// ---------------------------------------------------------------------------
// Launch. Inputs: x_ri, Wf, bf, Wi, bi, Wd, bd, A_real, A_imag, B_real, B_imag
// ---------------------------------------------------------------------------
extern "C" void kernel_launch(void* const* d_in, const int* in_sizes, int n_in,
                              void* d_out, int out_size) {
    (void)in_sizes; (void)n_in; (void)out_size;
    const float* x      = (const float*)d_in[0];
    const float* Wf     = (const float*)d_in[1];
    const float* bf     = (const float*)d_in[2];
    const float* Wi     = (const float*)d_in[3];
    const float* bi     = (const float*)d_in[4];
    const float* Wd     = (const float*)d_in[5];
    const float* bd     = (const float*)d_in[6];
    const float* A_real = (const float*)d_in[7];
    const float* A_imag = (const float*)d_in[8];
    const float* B_real = (const float*)d_in[9];
    const float* B_imag = (const float*)d_in[10];
    float* out = (float*)d_out;

    cudaFuncSetAttribute(fused_main, cudaFuncAttributeMaxDynamicSharedMemorySize,
                         SMEM_BYTES);

    pack_w<<<96, 256>>>(Wf, Wi, Wd);
    freq_rows<<<128 * 7, 64>>>(A_real, A_imag, B_real, B_imag);
    freq_cols<<<128 * 128, 64>>>();
    fused_main<<<16 * 128, 256, SMEM_BYTES>>>(x, bf, bi, bd, out);
}

// round 9
// speedup vs baseline: 1.6104x; 1.0002x over previous
#include <cuda_runtime.h>
#include <cstdint>

// ============================================================================
// StableFourierConvSSM fused kernel, round 7 — byte-identical resubmit of
// round 6 (infra "container failed twice", same pure-infra signature as
// round 1; no ptxas/harness output implicating the kernel).
// Base = round 4 (351us, smem-staged W panels — round 5 proved per-thread LDG
// B-frags are a regression). Changes vs round 4:
//   - sX and sW both pair-interleaved (k, k+4) float2, stride 68 (=4 mod 16,
//     conflict-free LDS.64 in both phases): A-frags 4xLDS.64, B-frags
//     4xLDS.64 per gate per kt (was 16x LDS.32 + 8 CVT).
//   - x pre-converted to tf32 at staging (CVT once, not per gate).
//   - epilogue reads exact fp32 x from global (L1/L2-hot tile).
//   - recurrence packed 2 sites per fma.rn.f32x2 (PTX 8.6, sm_100 family):
//     half the FFMA count, per-lane IEEE-identical.
// Shapes: B=16, H=128, W=128, C=64, C2=128, K=7, T=16.
// ============================================================================

#define SXP_STRIDE 68   // float2 stride; 68 % 16 == 4 -> conflict-free LDS.64
#define SWP_STRIDE 68
#define SMEM_BYTES (128 * SXP_STRIDE * 8 + 64 * SWP_STRIDE * 8 + 384 * 4)  // 105,984

// Packed freq kernels, layout [h][c][w] float4 = (Ar, Ai, Br, Bi)
__device__ float4 g_AB[128 * 64 * 128];
// Separable-DFT intermediate, layout [(u*7+q)*64 + c]
__device__ float g_GAr[128 * 7 * 64];
__device__ float g_GAi[128 * 7 * 64];
__device__ float g_GBr[128 * 7 * 64];
__device__ float g_GBi[128 * 7 * 64];
// Pre-paired tf32 W panels: [(gate*2+hf)][kp=64][jc=64] float2 = (k, k+4)
__device__ float2 g_Wpk[6 * 64 * 64];

__device__ __forceinline__ uint32_t f2tf32(float x) {
    uint32_t u;
    asm("cvt.rna.tf32.f32 %0, %1;" : "=r"(u) : "f"(x));
    return u;
}

__device__ __forceinline__ void mma_tf32(float d[4], const uint32_t a[4],
                                         uint32_t b0, uint32_t b1) {
    asm("mma.sync.aligned.m16n8k8.row.col.f32.tf32.tf32.f32 "
        "{%0,%1,%2,%3}, {%4,%5,%6,%7}, {%8,%9}, {%0,%1,%2,%3};"
        : "+f"(d[0]), "+f"(d[1]), "+f"(d[2]), "+f"(d[3])
        : "r"(a[0]), "r"(a[1]), "r"(a[2]), "r"(a[3]), "r"(b0), "r"(b1));
}

// ---- packed f32x2 (PTX ISA 8.6, sm_100 family) ----
__device__ __forceinline__ unsigned long long pk2(float lo, float hi) {
    unsigned long long r;
    asm("mov.b64 %0, {%1, %2};" : "=l"(r) : "f"(lo), "f"(hi));
    return r;
}
__device__ __forceinline__ void unpk2(unsigned long long v, float& lo, float& hi) {
    asm("mov.b64 {%0, %1}, %2;" : "=f"(lo), "=f"(hi) : "l"(v));
}
__device__ __forceinline__ unsigned long long ffma2(unsigned long long a,
                                                    unsigned long long b,
                                                    unsigned long long c) {
    unsigned long long d;
    asm("fma.rn.f32x2 %0, %1, %2, %3;" : "=l"(d) : "l"(a), "l"(b), "l"(c));
    return d;
}

__device__ __forceinline__ float sigm_f(float z) {
    return __fdividef(1.0f, 1.0f + __expf(-z));
}
__device__ __forceinline__ float softplus_f(float z) {
    return (z > 20.0f) ? z : __logf(1.0f + __expf(z));
}

// ---------------------------------------------------------------------------
// W pre-pack: permuted cols (adjacent = real/imag of one channel), tf32-
// rounded, (k, k+4) pair-interleaved.
// ---------------------------------------------------------------------------
__global__ void pack_w(const float* __restrict__ Wf, const float* __restrict__ Wi,
                       const float* __restrict__ Wd) {
    int idx = blockIdx.x * 256 + threadIdx.x;     // 0..24575
    int panel = idx >> 12;
    int rem = idx & 4095;
    int kp = rem >> 6, jc = rem & 63;
    int gate = panel >> 1, hf = panel & 1;
    const float* W = (gate == 0) ? Wf : (gate == 1) ? Wi : Wd;
    int k = (kp >> 2) * 8 + (kp & 3);
    int c = hf * 32 + (jc >> 1) + ((jc & 1) << 6);
    g_Wpk[idx] = make_float2(__uint_as_float(f2tf32(W[k * 128 + c])),
                             __uint_as_float(f2tf32(W[(k + 4) * 128 + c])));
}

// ---------------------------------------------------------------------------
// Stage 1: G[c,u,q] = sum_p kern[c,p,q] * exp(-2*pi*i * u*(p+60)/128)
// ---------------------------------------------------------------------------
__global__ void freq_rows(const float* __restrict__ A_real, const float* __restrict__ A_imag,
                          const float* __restrict__ B_real, const float* __restrict__ B_imag) {
    __shared__ float tc[128], ts[128];
    int t = threadIdx.x;  // 64
    for (int k = t; k < 128; k += 64) {
        float s, c;
        sincospif((float)k / 64.0f, &s, &c);
        tc[k] = c; ts[k] = s;
    }
    __syncthreads();
    int u = blockIdx.x / 7, q = blockIdx.x % 7, c = t;
    float gar = 0.f, gai = 0.f, gbr = 0.f, gbi = 0.f;
#pragma unroll
    for (int p = 0; p < 7; ++p) {
        int idx = (u * (p + 60)) & 127;
        float co = tc[idx], si = ts[idx];  // exp(-i t) = co - i si
        float kr = A_real[c * 49 + p * 7 + q], ki = A_imag[c * 49 + p * 7 + q];
        gar += kr * co + ki * si; gai += ki * co - kr * si;
        kr = B_real[c * 49 + p * 7 + q]; ki = B_imag[c * 49 + p * 7 + q];
        gbr += kr * co + ki * si; gbi += ki * co - kr * si;
    }
    int o = (u * 7 + q) * 64 + c;
    g_GAr[o] = gar; g_GAi[o] = gai; g_GBr[o] = gbr; g_GBi[o] = gbi;
}

// ---------------------------------------------------------------------------
// Stage 2: col DFT + A stability scaling; store packed [h][c][w] float4.
// ---------------------------------------------------------------------------
__global__ void freq_cols() {
    __shared__ float tc[128], ts[128];
    int t = threadIdx.x;  // 64
    for (int k = t; k < 128; k += 64) {
        float s, c;
        sincospif((float)k / 64.0f, &s, &c);
        tc[k] = c; ts[k] = s;
    }
    __syncthreads();
    int u = blockIdx.x >> 7, v = blockIdx.x & 127, c = t;
    float ar = 0.f, ai = 0.f, br = 0.f, bi = 0.f;
#pragma unroll
    for (int q = 0; q < 7; ++q) {
        int idx = (v * (q + 60)) & 127;
        float co = tc[idx], si = ts[idx];
        int o = (u * 7 + q) * 64 + c;
        float gr = g_GAr[o], gi = g_GAi[o];
        ar += gr * co + gi * si; ai += gi * co - gr * si;
        gr = g_GBr[o]; gi = g_GBi[o];
        br += gr * co + gi * si; bi += gi * co - gr * si;
    }
    float mag = sqrtf(ar * ar + ai * ai + 1e-8f);
    float sc = 0.95f * (1.0f / (1.0f + expf(-mag))) / (mag + 1e-8f);
    g_AB[(u * 64 + c) * 128 + v] = make_float4(ar * sc, ai * sc, br, bi);
}

// ---------------------------------------------------------------------------
// Fused main. One CTA per (b,h): M=128 w-rows, K=128, 3 gate GEMMs N=64/hf.
// 8 warps: wm=warp>>1 (32-row strip), wn=warp&1 (32-col half of 64-col panel).
// ---------------------------------------------------------------------------
__global__ void __launch_bounds__(256, 2)
fused_main(const float* __restrict__ x,
           const float* __restrict__ bf, const float* __restrict__ bi_,
           const float* __restrict__ bd, float* __restrict__ out) {
    extern __shared__ __align__(16) float smem[];
    float2* sXp = (float2*)smem;                               // [128][68] tf32 pairs
    float2* sWp = (float2*)(smem + 128 * SXP_STRIDE * 2);      // [64][68] W pairs
    float*  sB  = smem + 128 * SXP_STRIDE * 2 + 64 * SWP_STRIDE * 2;  // [384]

    const int tid = threadIdx.x;
    const int b = blockIdx.x >> 7;
    const int h = blockIdx.x & 127;
    const float* xg = x + ((size_t)(b * 128 + h)) * 16384;

    // ---- stage x: pair (k, k+4), PRE-CONVERTED to tf32 bits ----
    {
        const float4* x4 = (const float4*)xg;
        for (int i = tid; i < 2048; i += 256) {
            int w = i >> 4, j = i & 15;
            float4 lo = x4[w * 32 + 2 * j];
            float4 hi = x4[w * 32 + 2 * j + 1];
            float4 p0 = make_float4(__uint_as_float(f2tf32(lo.x)), __uint_as_float(f2tf32(hi.x)),
                                    __uint_as_float(f2tf32(lo.y)), __uint_as_float(f2tf32(hi.y)));
            float4 p1 = make_float4(__uint_as_float(f2tf32(lo.z)), __uint_as_float(f2tf32(hi.z)),
                                    __uint_as_float(f2tf32(lo.w)), __uint_as_float(f2tf32(hi.w)));
            float4* d = (float4*)(sXp + w * SXP_STRIDE + 4 * j);
            d[0] = p0; d[1] = p1;
        }
        for (int i = tid; i < 384; i += 256)
            sB[i] = (i < 128) ? bf[i] : (i < 256) ? bi_[i - 128] : bd[i - 256];
    }

    const int lane = tid & 31;
    const int warp = tid >> 5;
    const int g = lane >> 2;       // row within 8
    const int t4 = lane & 3;
    const int wm = warp >> 1;      // 32-row strip
    const int wn = warp & 1;       // 32-col half
    const int rbase = wm * 32;

    for (int hf = 0; hf < 2; ++hf) {
        float acc[3][2][4][4];  // [gate][mtile][ntile][frag]
#pragma unroll
        for (int gate = 0; gate < 3; ++gate)
#pragma unroll
            for (int mt = 0; mt < 2; ++mt)
#pragma unroll
                for (int nt = 0; nt < 4; ++nt)
#pragma unroll
                    for (int r = 0; r < 4; ++r)
                        acc[gate][mt][nt][r] = 0.0f;

        for (int gate = 0; gate < 3; ++gate) {
            __syncthreads();  // prev panel consumed (and x staged, first time)
            // stage pre-paired W panel: straight float4 copy with stride-68
            {
                const float4* src = (const float4*)(g_Wpk + (gate * 2 + hf) * 4096);
                for (int i = tid; i < 2048; i += 256) {
                    int kp = i >> 5, jc = (2 * i) & 63;
                    *(float4*)(sWp + kp * SWP_STRIDE + jc) = src[i];
                }
            }
            __syncthreads();

#pragma unroll 4
            for (int kt = 0; kt < 16; ++kt) {
                const int kp = kt * 4 + t4;
                uint32_t a[2][4];
#pragma unroll
                for (int mt = 0; mt < 2; ++mt) {
                    float2 lo = sXp[(rbase + 16 * mt + g) * SXP_STRIDE + kp];
                    float2 hi = sXp[(rbase + 16 * mt + g + 8) * SXP_STRIDE + kp];
                    a[mt][0] = __float_as_uint(lo.x);
                    a[mt][1] = __float_as_uint(hi.x);
                    a[mt][2] = __float_as_uint(lo.y);
                    a[mt][3] = __float_as_uint(hi.y);
                }
                const int bofs = kp * SWP_STRIDE + wn * 32 + g;
#pragma unroll
                for (int nt = 0; nt < 4; ++nt) {
                    float2 bb = sWp[bofs + nt * 8];
                    mma_tf32(acc[gate][0][nt], a[0],
                             __float_as_uint(bb.x), __float_as_uint(bb.y));
                    mma_tf32(acc[gate][1][nt], a[1],
                             __float_as_uint(bb.x), __float_as_uint(bb.y));
                }
            }
        }

        // ---- epilogue: activations + complex input + packed T=16 recurrence
#pragma unroll
        for (int mt = 0; mt < 2; ++mt)
#pragma unroll
            for (int nt = 0; nt < 4; ++nt) {
                const int m = hf * 32 + wn * 16 + nt * 4 + t4;  // channel 0..63
                const float bfr = sB[m] + 2.0f, bfi = sB[m + 64] + 2.0f;
                const float bir = sB[128 + m], bii = sB[128 + m + 64];
                const float bdr = sB[256 + m], bdi = sB[256 + m + 64];

                float M11[2], M12[2], M21[2], M22[2], IR[2], II[2];
                int wrow[2];
#pragma unroll
                for (int rr = 0; rr < 2; ++rr) {
                    const int w = rbase + 16 * mt + g + 8 * rr;
                    wrow[rr] = w;
                    float fg_r = sigm_f(acc[0][mt][nt][2 * rr] + bfr);
                    float fg_i = sigm_f(acc[0][mt][nt][2 * rr + 1] + bfi);
                    float ig_r = sigm_f(acc[1][mt][nt][2 * rr] + bir);
                    float ig_i = sigm_f(acc[1][mt][nt][2 * rr + 1] + bii);
                    float dl_r = 0.1f * softplus_f(acc[2][mt][nt][2 * rr] + bdr);
                    float dl_i = 0.1f * softplus_f(acc[2][mt][nt][2 * rr + 1] + bdi);

                    float x_r = xg[w * 128 + m];        // exact fp32 (L1/L2 hot)
                    float x_i = xg[w * 128 + m + 64];
                    float4 AB = g_AB[(h * 64 + m) * 128 + w];  // (Ar,Ai,Br,Bi)

                    float Bx_r = AB.z * x_r - AB.w * x_i;
                    float Bx_i = AB.z * x_i + AB.w * x_r;
                    IR[rr] = dl_r * ig_r * Bx_r;
                    II[rr] = dl_i * ig_i * Bx_i;
                    M11[rr] = fg_r * AB.x; M12[rr] = -fg_r * AB.y;
                    M21[rr] = fg_i * AB.y; M22[rr] = fg_i * AB.x;
                }

                // two independent sites per f32x2 lane-pair
                unsigned long long pm11 = pk2(M11[0], M11[1]);
                unsigned long long pm12 = pk2(M12[0], M12[1]);
                unsigned long long pm21 = pk2(M21[0], M21[1]);
                unsigned long long pm22 = pk2(M22[0], M22[1]);
                unsigned long long pir  = pk2(IR[0], IR[1]);
                unsigned long long pii  = pk2(II[0], II[1]);
                unsigned long long vr = pir, vi = pii;  // step 1 from h0 = 0
#pragma unroll
                for (int t = 1; t < 16; ++t) {
                    unsigned long long nr = ffma2(pm11, vr, ffma2(pm12, vi, pir));
                    unsigned long long ni = ffma2(pm21, vr, ffma2(pm22, vi, pii));
                    vr = nr; vi = ni;
                }
                float hr0, hr1, hi0, hi1;
                unpk2(vr, hr0, hr1);
                unpk2(vi, hi0, hi1);

                size_t ob0 = ((size_t)(b * 128 + h) * 128 + wrow[0]) * 128;
                size_t ob1 = ((size_t)(b * 128 + h) * 128 + wrow[1]) * 128;
                out[ob0 + m] = hr0; out[ob0 + m + 64] = hi0;
                out[ob1 + m] = hr1; out[ob1 + m + 64] = hi1;
            }
    }
}

// ---------------------------------------------------------------------------
// Launch. Inputs: x_ri, Wf, bf, Wi, bi, Wd, bd, A_real, A_imag, B_real, B_imag
// ---------------------------------------------------------------------------
extern "C" void kernel_launch(void* const* d_in, const int* in_sizes, int n_in,
                              void* d_out, int out_size) {
    (void)in_sizes; (void)n_in; (void)out_size;
    const float* x      = (const float*)d_in[0];
    const float* Wf     = (const float*)d_in[1];
    const float* bf     = (const float*)d_in[2];
    const float* Wi     = (const float*)d_in[3];
    const float* bi     = (const float*)d_in[4];
    const float* Wd     = (const float*)d_in[5];
    const float* bd     = (const float*)d_in[6];
    const float* A_real = (const float*)d_in[7];
    const float* A_imag = (const float*)d_in[8];
    const float* B_real = (const float*)d_in[9];
    const float* B_imag = (const float*)d_in[10];
    float* out = (float*)d_out;

    cudaFuncSetAttribute(fused_main, cudaFuncAttributeMaxDynamicSharedMemorySize,
                         SMEM_BYTES);

    pack_w<<<96, 256>>>(Wf, Wi, Wd);
    freq_rows<<<128 * 7, 64>>>(A_real, A_imag, B_real, B_imag);
    freq_cols<<<128 * 128, 64>>>();
    fused_main<<<16 * 128, 256, SMEM_BYTES>>>(x, bf, bi, bd, out);
}